// round 12
// baseline (speedup 1.0000x reference)
#include <cuda_runtime.h>

#define BATCH 2048
#define NPTS  4095
#define TPB   384
#define CH    1536          // elements per pass
#define LEPT  4             // TPB*LEPT = CH
#define NPASS 3             // 3*1536 = 4608 >= 4095
#define NWARP (TPB/32)      // 12

__device__ float g_partial[BATCH];
__device__ int   g_count = 0;

// 3 distinct buffers x 3 components x 1536 floats = 54 KB
#define SMEM_BYTES (3 * 3 * CH * 4)

extern __shared__ __align__(16) float sstage[];

__device__ __forceinline__ void phaseA(int p,
                                       float* __restrict__ bx,
                                       float* __restrict__ by,
                                       float* __restrict__ bz,
                                       const float* __restrict__ s3b,
                                       const float* __restrict__ s2b,
                                       const float* __restrict__ dfb,
                                       int t)
{
    #pragma unroll
    for (int k = 0; k < LEPT; k++) {
        const int i = t + k * TPB;          // 0..1535, coalesced
        const int g = i + p * CH;
        float vx = 0.f, vy = 0.f, vz = 0.f;
        if (g < NPTS) {
            float r3  = s3b[g];
            float th3 = s3b[g + NPTS];
            float ph3 = s3b[g + 2 * NPTS];
            float r2  = s2b[g];
            float th2 = s2b[g + NPTS];
            float ph2 = s2b[g + 2 * NPTS];
            float dt  = dfb[g];
            float dp  = dfb[g + NPTS];

            float st, ct, sp, cp;
            __sincosf(th3 + dt, &st, &ct);
            __sincosf(ph3 + dp, &sp, &cp);
            float rst = r3 * st;
            vx = rst * cp; vy = rst * sp; vz = r3 * ct;
            __sincosf(th2, &st, &ct);
            __sincosf(ph2, &sp, &cp);
            rst = r2 * st;
            vx -= rst * cp; vy -= rst * sp; vz -= r2 * ct;
        }
        bx[i] = vx; by[i] = vy; bz[i] = vz;
    }
}

__global__ void __launch_bounds__(TPB, 4)
mpd_fused_kernel(const float* __restrict__ o3,
                 const float* __restrict__ s3,
                 const float* __restrict__ o2,
                 const float* __restrict__ s2,
                 const float* __restrict__ df,
                 float* __restrict__ out)
{
    __shared__ float wt[2][3][NWARP];       // ping-pong warp-total slots
    __shared__ float red[NWARP];
    __shared__ int   is_last;

    const int b = blockIdx.x;
    const int t = threadIdx.x;
    const unsigned lane = t & 31u;
    const unsigned warp = t >> 5;

    const float* __restrict__ s3b = s3 + (size_t)b * (3 * NPTS);
    const float* __restrict__ s2b = s2 + (size_t)b * (3 * NPTS);
    const float* __restrict__ dfb = df + (size_t)b * (2 * NPTS);

    // prologue: pass 0 -> buffer 0
    phaseA(0, sstage, sstage + CH, sstage + 2 * CH, s3b, s2b, dfb, t);
    __syncthreads();

    const float dx = o3[b * 3 + 0] - o2[b * 3 + 0];
    const float dy = o3[b * 3 + 1] - o2[b * 3 + 1];
    const float dz = o3[b * 3 + 2] - o2[b * 3 + 2];
    float offx = dx, offy = dy, offz = dz;
    float acc = 0.f;
    if (t == 0) acc = fabsf(dx) + fabsf(dy) + fabsf(dz);   // j=0 (origin)

    const int base = LEPT * t;               // float4 slot, 16B aligned

    #pragma unroll
    for (int p = 0; p < NPASS; p++) {
        float* cbx = sstage + (p * 3 + 0) * CH;
        float* cby = sstage + (p * 3 + 1) * CH;
        float* cbz = sstage + (p * 3 + 2) * CH;

        // issue next pass's load burst FIRST (covers this pass's scan)
        if (p + 1 < NPASS) {
            float* nbx = sstage + ((p + 1) * 3 + 0) * CH;
            float* nby = sstage + ((p + 1) * 3 + 1) * CH;
            float* nbz = sstage + ((p + 1) * 3 + 2) * CH;
            phaseA(p + 1, nbx, nby, nbz, s3b, s2b, dfb, t);
        }

        // ---- B_a: thread totals (LDS.128) + warp scan ----
        float4 X = *reinterpret_cast<const float4*>(cbx + base);
        float4 Y = *reinterpret_cast<const float4*>(cby + base);
        float4 Z = *reinterpret_cast<const float4*>(cbz + base);
        const float tx = (X.x + X.y) + (X.z + X.w);
        const float ty = (Y.x + Y.y) + (Y.z + Y.w);
        const float tz = (Z.x + Z.y) + (Z.z + Z.w);

        float ix = tx, iy = ty, iz = tz;
        #pragma unroll
        for (int o = 1; o < 32; o <<= 1) {
            float ax = __shfl_up_sync(0xFFFFFFFFu, ix, o);
            float ay = __shfl_up_sync(0xFFFFFFFFu, iy, o);
            float az = __shfl_up_sync(0xFFFFFFFFu, iz, o);
            if (lane >= (unsigned)o) { ix += ax; iy += ay; iz += az; }
        }
        const int s = p & 1;
        if (lane == 31) {
            wt[s][0][warp] = ix; wt[s][1][warp] = iy; wt[s][2][warp] = iz;
        }
        __syncthreads();                     // one barrier per pass

        // ---- B_b: redundant warp-total scan + abs sweep ----
        float px = (lane < NWARP) ? wt[s][0][lane] : 0.f;
        float py = (lane < NWARP) ? wt[s][1][lane] : 0.f;
        float pz = (lane < NWARP) ? wt[s][2][lane] : 0.f;
        #pragma unroll
        for (int o = 1; o < 16; o <<= 1) {   // covers 12 warps
            float ax = __shfl_up_sync(0xFFFFFFFFu, px, o);
            float ay = __shfl_up_sync(0xFFFFFFFFu, py, o);
            float az = __shfl_up_sync(0xFFFFFFFFu, pz, o);
            if (lane >= (unsigned)o) { px += ax; py += ay; pz += az; }
        }
        const unsigned src = (warp == 0) ? 0u : (warp - 1u);
        float wpx = __shfl_sync(0xFFFFFFFFu, px, src);
        float wpy = __shfl_sync(0xFFFFFFFFu, py, src);
        float wpz = __shfl_sync(0xFFFFFFFFu, pz, src);

        float ox = offx + (ix - tx) + ((warp == 0) ? 0.f : wpx);
        float oy = offy + (iy - ty) + ((warp == 0) ? 0.f : wpy);
        float oz = offz + (iz - tz) + ((warp == 0) ? 0.f : wpz);

        const int gbase = p * CH + base;
        float xs[LEPT] = {X.x, X.y, X.z, X.w};
        float ys[LEPT] = {Y.x, Y.y, Y.z, Y.w};
        float zs[LEPT] = {Z.x, Z.y, Z.z, Z.w};
        #pragma unroll
        for (int k = 0; k < LEPT; k++) {
            ox += xs[k]; oy += ys[k]; oz += zs[k];
            if (gbase + k < NPTS)
                acc += fabsf(ox) + fabsf(oy) + fabsf(oz);
        }

        // advance running offset by this pass's block total (lane NWARP-1)
        offx += __shfl_sync(0xFFFFFFFFu, px, NWARP - 1);
        offy += __shfl_sync(0xFFFFFFFFu, py, NWARP - 1);
        offz += __shfl_sync(0xFFFFFFFFu, pz, NWARP - 1);
    }

    // ---- block reduce ----
    #pragma unroll
    for (int o = 16; o > 0; o >>= 1)
        acc += __shfl_down_sync(0xFFFFFFFFu, acc, o);
    if (lane == 0) red[warp] = acc;
    __syncthreads();
    if (warp == 0) {
        float a = (lane < NWARP) ? red[lane] : 0.f;
        #pragma unroll
        for (int o = 16; o > 0; o >>= 1)
            a += __shfl_down_sync(0xFFFFFFFFu, a, o);
        if (lane == 0) g_partial[b] = a * (1.0f / (NPTS + 1));
    }

    // ---- fused deterministic final reduction in the last block ----
    if (t == 0) {
        __threadfence();
        int ticket = atomicAdd(&g_count, 1);
        is_last = (ticket == (int)gridDim.x - 1) ? 1 : 0;
    }
    __syncthreads();
    if (is_last) {
        float a = 0.f;
        #pragma unroll
        for (int k = 0; k < 6; k++) {        // 6*384 = 2304 >= 2048
            const int idx = t + k * TPB;
            if (idx < BATCH) a += __ldcg(&g_partial[idx]);
        }
        #pragma unroll
        for (int o = 16; o > 0; o >>= 1)
            a += __shfl_down_sync(0xFFFFFFFFu, a, o);
        if (lane == 0) red[warp] = a;
        __syncthreads();
        if (warp == 0) {
            float v = (lane < NWARP) ? red[lane] : 0.f;
            #pragma unroll
            for (int o = 16; o > 0; o >>= 1)
                v += __shfl_down_sync(0xFFFFFFFFu, v, o);
            if (lane == 0) {
                out[0] = v;
                atomicExch(&g_count, 0);   // reset for next graph replay
            }
        }
    }
}

extern "C" void kernel_launch(void* const* d_in, const int* in_sizes, int n_in,
                              void* d_out, int out_size)
{
    const float* o3 = (const float*)d_in[0];  // origin_3D        (B,3,1)
    const float* s3 = (const float*)d_in[1];  // spherical_3D     (B,3,N)
    const float* o2 = (const float*)d_in[2];  // origin_2D        (B,3,1)
    const float* s2 = (const float*)d_in[3];  // spherical_2D     (B,3,N)
    const float* df = (const float*)d_in[4];  // deformation_field(B,2,N)
    float* out = (float*)d_out;

    cudaFuncSetAttribute(mpd_fused_kernel,
                         cudaFuncAttributeMaxDynamicSharedMemorySize, SMEM_BYTES);
    mpd_fused_kernel<<<BATCH, TPB, SMEM_BYTES>>>(o3, s3, o2, s2, df, out);
}

// round 13
// speedup vs baseline: 1.1653x; 1.1653x over previous
#include <cuda_runtime.h>

#define BATCH 2048
#define NPTS  4095
#define TPB   512
#define CH    2048          // elements per quarter-pass
#define LEPT  4             // TPB*LEPT = CH
#define NQ    4             // 2 halves x 2 batches per block
#define NWARP (TPB/32)      // 16
#define GRID  (BATCH/2)

__device__ float g_partial[BATCH];
__device__ int   g_count = 0;

// 2 ping-pong buffers x 3 components x 2048 floats = 48 KB
#define SMEM_BYTES (2 * 3 * CH * 4)

extern __shared__ __align__(16) float sstage[];

__device__ __forceinline__ void phaseA(const float* __restrict__ s3b,
                                       const float* __restrict__ s2b,
                                       const float* __restrict__ dfb,
                                       int half,
                                       float* __restrict__ bx,
                                       float* __restrict__ by,
                                       float* __restrict__ bz,
                                       int t)
{
    #pragma unroll
    for (int k = 0; k < LEPT; k++) {
        const int i = t + k * TPB;          // 0..2047, coalesced
        const int g = i + half * CH;
        float vx = 0.f, vy = 0.f, vz = 0.f;
        if (g < NPTS) {                      // only g==4095 (half==1) fails
            float r3  = s3b[g];
            float th3 = s3b[g + NPTS];
            float ph3 = s3b[g + 2 * NPTS];
            float r2  = s2b[g];
            float th2 = s2b[g + NPTS];
            float ph2 = s2b[g + 2 * NPTS];
            float dt  = dfb[g];
            float dp  = dfb[g + NPTS];

            float st, ct, sp, cp;
            __sincosf(th3 + dt, &st, &ct);
            __sincosf(ph3 + dp, &sp, &cp);
            float rst = r3 * st;
            vx = rst * cp; vy = rst * sp; vz = r3 * ct;
            __sincosf(th2, &st, &ct);
            __sincosf(ph2, &sp, &cp);
            rst = r2 * st;
            vx -= rst * cp; vy -= rst * sp; vz -= r2 * ct;
        }
        bx[i] = vx; by[i] = vy; bz[i] = vz;
    }
}

__global__ void __launch_bounds__(TPB, 3)
mpd_fused_kernel(const float* __restrict__ o3,
                 const float* __restrict__ s3,
                 const float* __restrict__ o2,
                 const float* __restrict__ s2,
                 const float* __restrict__ df,
                 float* __restrict__ out)
{
    __shared__ float wt[2][3][NWARP];        // ping-pong warp-total slots
    __shared__ float red0[NWARP], red1[NWARP];
    __shared__ int   is_last;

    const int b0 = blockIdx.x * 2;           // batches b0, b0+1
    const int t = threadIdx.x;
    const unsigned lane = t & 31u;
    const unsigned warp = t >> 5;

    const float* __restrict__ s3b0 = s3 + (size_t)b0 * (3 * NPTS);
    const float* __restrict__ s2b0 = s2 + (size_t)b0 * (3 * NPTS);
    const float* __restrict__ dfb0 = df + (size_t)b0 * (2 * NPTS);
    const float* __restrict__ s3b1 = s3b0 + 3 * NPTS;
    const float* __restrict__ s2b1 = s2b0 + 3 * NPTS;
    const float* __restrict__ dfb1 = dfb0 + 2 * NPTS;

    // prologue: q=0 (batch0, half0) -> buffer 0
    phaseA(s3b0, s2b0, dfb0, 0, sstage, sstage + CH, sstage + 2 * CH, t);
    __syncthreads();

    float offx = o3[b0 * 3 + 0] - o2[b0 * 3 + 0];
    float offy = o3[b0 * 3 + 1] - o2[b0 * 3 + 1];
    float offz = o3[b0 * 3 + 2] - o2[b0 * 3 + 2];
    float acc0 = 0.f, acc1 = 0.f;
    if (t == 0) acc0 = fabsf(offx) + fabsf(offy) + fabsf(offz);  // batch0 j=0

    const int base = LEPT * t;               // float4 slot, 16B aligned

    #pragma unroll
    for (int q = 0; q < NQ; q++) {
        const int qb = q >> 1, qh = q & 1;   // batch, half (compile-time)
        const int s  = q & 1;                // buffer / wt slot

        float* cbx = sstage + (s * 3 + 0) * CH;
        float* cby = sstage + (s * 3 + 1) * CH;
        float* cbz = sstage + (s * 3 + 2) * CH;

        // issue next quarter's load burst FIRST (covers this quarter's scan)
        if (q + 1 < NQ) {
            const int nb = (q + 1) >> 1, nh = (q + 1) & 1;
            const int ns = (q + 1) & 1;
            float* nbx = sstage + (ns * 3 + 0) * CH;
            float* nby = sstage + (ns * 3 + 1) * CH;
            float* nbz = sstage + (ns * 3 + 2) * CH;
            phaseA(nb ? s3b1 : s3b0, nb ? s2b1 : s2b0, nb ? dfb1 : dfb0,
                   nh, nbx, nby, nbz, t);
        }

        // batch rollover: reset running offset for batch1
        if (q == 2) {
            offx = o3[(b0 + 1) * 3 + 0] - o2[(b0 + 1) * 3 + 0];
            offy = o3[(b0 + 1) * 3 + 1] - o2[(b0 + 1) * 3 + 1];
            offz = o3[(b0 + 1) * 3 + 2] - o2[(b0 + 1) * 3 + 2];
            if (t == 0) acc1 = fabsf(offx) + fabsf(offy) + fabsf(offz);
        }

        // ---- B_a: ONE smem read (kept in regs), totals + warp scan ----
        float4 X = *reinterpret_cast<const float4*>(cbx + base);
        float4 Y = *reinterpret_cast<const float4*>(cby + base);
        float4 Z = *reinterpret_cast<const float4*>(cbz + base);
        const float tx = (X.x + X.y) + (X.z + X.w);
        const float ty = (Y.x + Y.y) + (Y.z + Y.w);
        const float tz = (Z.x + Z.y) + (Z.z + Z.w);

        float ix = tx, iy = ty, iz = tz;
        #pragma unroll
        for (int o = 1; o < 32; o <<= 1) {
            float ax = __shfl_up_sync(0xFFFFFFFFu, ix, o);
            float ay = __shfl_up_sync(0xFFFFFFFFu, iy, o);
            float az = __shfl_up_sync(0xFFFFFFFFu, iz, o);
            if (lane >= (unsigned)o) { ix += ax; iy += ay; iz += az; }
        }
        if (lane == 31) {
            wt[s][0][warp] = ix; wt[s][1][warp] = iy; wt[s][2][warp] = iz;
        }
        __syncthreads();                     // bar(q): fences wt[s] AND buffer reuse

        // ---- B_b: cross-warp scan + abs sweep from registers ----
        float px = (lane < NWARP) ? wt[s][0][lane] : 0.f;
        float py = (lane < NWARP) ? wt[s][1][lane] : 0.f;
        float pz = (lane < NWARP) ? wt[s][2][lane] : 0.f;
        #pragma unroll
        for (int o = 1; o < NWARP; o <<= 1) {
            float ax = __shfl_up_sync(0xFFFFFFFFu, px, o);
            float ay = __shfl_up_sync(0xFFFFFFFFu, py, o);
            float az = __shfl_up_sync(0xFFFFFFFFu, pz, o);
            if (lane >= (unsigned)o) { px += ax; py += ay; pz += az; }
        }
        const unsigned src = (warp == 0) ? 0u : (warp - 1u);
        float wpx = __shfl_sync(0xFFFFFFFFu, px, src);
        float wpy = __shfl_sync(0xFFFFFFFFu, py, src);
        float wpz = __shfl_sync(0xFFFFFFFFu, pz, src);

        float ox = offx + (ix - tx) + ((warp == 0) ? 0.f : wpx);
        float oy = offy + (iy - ty) + ((warp == 0) ? 0.f : wpy);
        float oz = offz + (iz - tz) + ((warp == 0) ? 0.f : wpz);

        float a = 0.f;
        const int gbase = qh * CH + base;
        float xs[LEPT] = {X.x, X.y, X.z, X.w};
        float ys[LEPT] = {Y.x, Y.y, Y.z, Y.w};
        float zs[LEPT] = {Z.x, Z.y, Z.z, Z.w};
        #pragma unroll
        for (int k = 0; k < LEPT; k++) {
            ox += xs[k]; oy += ys[k]; oz += zs[k];
            if (gbase + k < NPTS)
                a += fabsf(ox) + fabsf(oy) + fabsf(oz);
        }
        if (qb == 0) acc0 += a; else acc1 += a;

        // advance running offset by this quarter's block total
        offx += __shfl_sync(0xFFFFFFFFu, px, NWARP - 1);
        offy += __shfl_sync(0xFFFFFFFFu, py, NWARP - 1);
        offz += __shfl_sync(0xFFFFFFFFu, pz, NWARP - 1);
    }

    // ---- block reduce of acc0 and acc1 (merged) ----
    #pragma unroll
    for (int o = 16; o > 0; o >>= 1) {
        acc0 += __shfl_down_sync(0xFFFFFFFFu, acc0, o);
        acc1 += __shfl_down_sync(0xFFFFFFFFu, acc1, o);
    }
    if (lane == 0) { red0[warp] = acc0; red1[warp] = acc1; }
    __syncthreads();
    if (warp == 0) {
        float a0 = (lane < NWARP) ? red0[lane] : 0.f;
        float a1 = (lane < NWARP) ? red1[lane] : 0.f;
        #pragma unroll
        for (int o = 16; o > 0; o >>= 1) {
            a0 += __shfl_down_sync(0xFFFFFFFFu, a0, o);
            a1 += __shfl_down_sync(0xFFFFFFFFu, a1, o);
        }
        if (lane == 0) {
            g_partial[b0]     = a0 * (1.0f / (NPTS + 1));
            g_partial[b0 + 1] = a1 * (1.0f / (NPTS + 1));
        }
    }

    // ---- fused deterministic final reduction in the last block ----
    if (t == 0) {
        __threadfence();
        int ticket = atomicAdd(&g_count, 1);
        is_last = (ticket == (int)gridDim.x - 1) ? 1 : 0;
    }
    __syncthreads();
    if (is_last) {
        float a = __ldcg(&g_partial[t])
                + __ldcg(&g_partial[t + TPB])
                + __ldcg(&g_partial[t + 2 * TPB])
                + __ldcg(&g_partial[t + 3 * TPB]);
        #pragma unroll
        for (int o = 16; o > 0; o >>= 1)
            a += __shfl_down_sync(0xFFFFFFFFu, a, o);
        if (lane == 0) red0[warp] = a;
        __syncthreads();
        if (warp == 0) {
            float v = (lane < NWARP) ? red0[lane] : 0.f;
            #pragma unroll
            for (int o = 16; o > 0; o >>= 1)
                v += __shfl_down_sync(0xFFFFFFFFu, v, o);
            if (lane == 0) {
                out[0] = v;
                atomicExch(&g_count, 0);   // reset for next graph replay
            }
        }
    }
}

extern "C" void kernel_launch(void* const* d_in, const int* in_sizes, int n_in,
                              void* d_out, int out_size)
{
    const float* o3 = (const float*)d_in[0];  // origin_3D        (B,3,1)
    const float* s3 = (const float*)d_in[1];  // spherical_3D     (B,3,N)
    const float* o2 = (const float*)d_in[2];  // origin_2D        (B,3,1)
    const float* s2 = (const float*)d_in[3];  // spherical_2D     (B,3,N)
    const float* df = (const float*)d_in[4];  // deformation_field(B,2,N)
    float* out = (float*)d_out;

    cudaFuncSetAttribute(mpd_fused_kernel,
                         cudaFuncAttributeMaxDynamicSharedMemorySize, SMEM_BYTES);
    mpd_fused_kernel<<<GRID, TPB, SMEM_BYTES>>>(o3, s3, o2, s2, df, out);
}

// round 14
// speedup vs baseline: 1.2967x; 1.1128x over previous
#include <cuda_runtime.h>

#define BATCH 2048
#define NPTS  4095
#define TPB   256
#define CH    1024          // elements per pass
#define LEPT  4             // TPB*LEPT = CH
#define NPASS 4             // 4*1024 = 4096 >= 4095
#define NWARP (TPB/32)      // 8

__device__ float g_partial[BATCH];
__device__ int   g_count = 0;

// 2 ping-pong buffers x 3 components x 1024 floats = 24 KB
#define SMEM_BYTES (2 * 3 * CH * 4)

extern __shared__ __align__(16) float sstage[];

__device__ __forceinline__ void phaseA(int p,
                                       float* __restrict__ bx,
                                       float* __restrict__ by,
                                       float* __restrict__ bz,
                                       const float* __restrict__ s3b,
                                       const float* __restrict__ s2b,
                                       const float* __restrict__ dfb,
                                       int t)
{
    #pragma unroll
    for (int k = 0; k < LEPT; k++) {
        const int i = t + k * TPB;          // 0..1023, coalesced
        const int g = i + p * CH;
        float vx = 0.f, vy = 0.f, vz = 0.f;
        if (g < NPTS) {                      // only g==4095 (p==3) fails
            float r3  = s3b[g];
            float th3 = s3b[g + NPTS];
            float ph3 = s3b[g + 2 * NPTS];
            float r2  = s2b[g];
            float th2 = s2b[g + NPTS];
            float ph2 = s2b[g + 2 * NPTS];
            float dt  = dfb[g];
            float dp  = dfb[g + NPTS];

            float st, ct, sp, cp;
            __sincosf(th3 + dt, &st, &ct);
            __sincosf(ph3 + dp, &sp, &cp);
            float rst = r3 * st;
            vx = rst * cp; vy = rst * sp; vz = r3 * ct;
            __sincosf(th2, &st, &ct);
            __sincosf(ph2, &sp, &cp);
            rst = r2 * st;
            vx -= rst * cp; vy -= rst * sp; vz -= r2 * ct;
        }
        bx[i] = vx; by[i] = vy; bz[i] = vz;
    }
}

__global__ void __launch_bounds__(TPB, 5)
mpd_fused_kernel(const float* __restrict__ o3,
                 const float* __restrict__ s3,
                 const float* __restrict__ o2,
                 const float* __restrict__ s2,
                 const float* __restrict__ df,
                 float* __restrict__ out)
{
    __shared__ float wt[2][3][NWARP];        // ping-pong warp-total slots
    __shared__ float red[NWARP];
    __shared__ int   is_last;

    const int b = blockIdx.x;
    const int t = threadIdx.x;
    const unsigned lane = t & 31u;
    const unsigned warp = t >> 5;

    const float* __restrict__ s3b = s3 + (size_t)b * (3 * NPTS);
    const float* __restrict__ s2b = s2 + (size_t)b * (3 * NPTS);
    const float* __restrict__ dfb = df + (size_t)b * (2 * NPTS);

    // prologue: pass 0 -> buffer 0
    phaseA(0, sstage, sstage + CH, sstage + 2 * CH, s3b, s2b, dfb, t);
    __syncthreads();

    const float dx = o3[b * 3 + 0] - o2[b * 3 + 0];
    const float dy = o3[b * 3 + 1] - o2[b * 3 + 1];
    const float dz = o3[b * 3 + 2] - o2[b * 3 + 2];
    float offx = dx, offy = dy, offz = dz;
    float acc = 0.f;
    if (t == 0) acc = fabsf(dx) + fabsf(dy) + fabsf(dz);   // j=0 (origin)

    const int base = LEPT * t;               // float4 slot, 16B aligned

    #pragma unroll
    for (int q = 0; q < NPASS; q++) {
        const int s = q & 1;                 // buffer / wt slot

        float* cbx = sstage + (s * 3 + 0) * CH;
        float* cby = sstage + (s * 3 + 1) * CH;
        float* cbz = sstage + (s * 3 + 2) * CH;

        // issue next pass's load burst FIRST (covers this pass's scan)
        if (q + 1 < NPASS) {
            const int ns = (q + 1) & 1;
            float* nbx = sstage + (ns * 3 + 0) * CH;
            float* nby = sstage + (ns * 3 + 1) * CH;
            float* nbz = sstage + (ns * 3 + 2) * CH;
            phaseA(q + 1, nbx, nby, nbz, s3b, s2b, dfb, t);
        }

        // ---- B_a: ONE smem read (kept in regs), totals + warp scan ----
        float4 X = *reinterpret_cast<const float4*>(cbx + base);
        float4 Y = *reinterpret_cast<const float4*>(cby + base);
        float4 Z = *reinterpret_cast<const float4*>(cbz + base);
        const float tx = (X.x + X.y) + (X.z + X.w);
        const float ty = (Y.x + Y.y) + (Y.z + Y.w);
        const float tz = (Z.x + Z.y) + (Z.z + Z.w);

        float ix = tx, iy = ty, iz = tz;
        #pragma unroll
        for (int o = 1; o < 32; o <<= 1) {
            float ax = __shfl_up_sync(0xFFFFFFFFu, ix, o);
            float ay = __shfl_up_sync(0xFFFFFFFFu, iy, o);
            float az = __shfl_up_sync(0xFFFFFFFFu, iz, o);
            if (lane >= (unsigned)o) { ix += ax; iy += ay; iz += az; }
        }
        if (lane == 31) {
            wt[s][0][warp] = ix; wt[s][1][warp] = iy; wt[s][2][warp] = iz;
        }
        __syncthreads();                     // bar(q): fences wt[s] AND buffer reuse

        // ---- B_b: cross-warp scan (8 totals) + abs sweep from registers ----
        float px = (lane < NWARP) ? wt[s][0][lane] : 0.f;
        float py = (lane < NWARP) ? wt[s][1][lane] : 0.f;
        float pz = (lane < NWARP) ? wt[s][2][lane] : 0.f;
        #pragma unroll
        for (int o = 1; o < NWARP; o <<= 1) {
            float ax = __shfl_up_sync(0xFFFFFFFFu, px, o);
            float ay = __shfl_up_sync(0xFFFFFFFFu, py, o);
            float az = __shfl_up_sync(0xFFFFFFFFu, pz, o);
            if (lane >= (unsigned)o) { px += ax; py += ay; pz += az; }
        }
        const unsigned src = (warp == 0) ? 0u : (warp - 1u);
        float wpx = __shfl_sync(0xFFFFFFFFu, px, src);
        float wpy = __shfl_sync(0xFFFFFFFFu, py, src);
        float wpz = __shfl_sync(0xFFFFFFFFu, pz, src);

        float ox = offx + (ix - tx) + ((warp == 0) ? 0.f : wpx);
        float oy = offy + (iy - ty) + ((warp == 0) ? 0.f : wpy);
        float oz = offz + (iz - tz) + ((warp == 0) ? 0.f : wpz);

        const int gbase = q * CH + base;
        float xs[LEPT] = {X.x, X.y, X.z, X.w};
        float ys[LEPT] = {Y.x, Y.y, Y.z, Y.w};
        float zs[LEPT] = {Z.x, Z.y, Z.z, Z.w};
        #pragma unroll
        for (int k = 0; k < LEPT; k++) {
            ox += xs[k]; oy += ys[k]; oz += zs[k];
            if (gbase + k < NPTS)
                acc += fabsf(ox) + fabsf(oy) + fabsf(oz);
        }

        // advance running offset by this pass's block total
        offx += __shfl_sync(0xFFFFFFFFu, px, NWARP - 1);
        offy += __shfl_sync(0xFFFFFFFFu, py, NWARP - 1);
        offz += __shfl_sync(0xFFFFFFFFu, pz, NWARP - 1);
    }

    // ---- block reduce ----
    #pragma unroll
    for (int o = 16; o > 0; o >>= 1)
        acc += __shfl_down_sync(0xFFFFFFFFu, acc, o);
    if (lane == 0) red[warp] = acc;
    __syncthreads();
    if (warp == 0) {
        float a = (lane < NWARP) ? red[lane] : 0.f;
        #pragma unroll
        for (int o = 16; o > 0; o >>= 1)
            a += __shfl_down_sync(0xFFFFFFFFu, a, o);
        if (lane == 0) g_partial[b] = a * (1.0f / (NPTS + 1));
    }

    // ---- fused deterministic final reduction in the last block ----
    if (t == 0) {
        __threadfence();
        int ticket = atomicAdd(&g_count, 1);
        is_last = (ticket == (int)gridDim.x - 1) ? 1 : 0;
    }
    __syncthreads();
    if (is_last) {
        float a = 0.f;
        #pragma unroll
        for (int k = 0; k < BATCH / TPB; k++)   // 8 loads of 256
            a += __ldcg(&g_partial[t + k * TPB]);
        #pragma unroll
        for (int o = 16; o > 0; o >>= 1)
            a += __shfl_down_sync(0xFFFFFFFFu, a, o);
        if (lane == 0) red[warp] = a;
        __syncthreads();
        if (warp == 0) {
            float v = (lane < NWARP) ? red[lane] : 0.f;
            #pragma unroll
            for (int o = 16; o > 0; o >>= 1)
                v += __shfl_down_sync(0xFFFFFFFFu, v, o);
            if (lane == 0) {
                out[0] = v;
                atomicExch(&g_count, 0);   // reset for next graph replay
            }
        }
    }
}

extern "C" void kernel_launch(void* const* d_in, const int* in_sizes, int n_in,
                              void* d_out, int out_size)
{
    const float* o3 = (const float*)d_in[0];  // origin_3D        (B,3,1)
    const float* s3 = (const float*)d_in[1];  // spherical_3D     (B,3,N)
    const float* o2 = (const float*)d_in[2];  // origin_2D        (B,3,1)
    const float* s2 = (const float*)d_in[3];  // spherical_2D     (B,3,N)
    const float* df = (const float*)d_in[4];  // deformation_field(B,2,N)
    float* out = (float*)d_out;

    cudaFuncSetAttribute(mpd_fused_kernel,
                         cudaFuncAttributeMaxDynamicSharedMemorySize, SMEM_BYTES);
    mpd_fused_kernel<<<BATCH, TPB, SMEM_BYTES>>>(o3, s3, o2, s2, df, out);
}

// round 15
// speedup vs baseline: 1.3282x; 1.0243x over previous
#include <cuda_runtime.h>

#define BATCH 2048
#define NPTS  4095
#define TPB   512
#define CH    2048          // elements per half-batch quarter
#define LEPT  4             // TPB*LEPT = CH
#define NWARP (TPB/32)      // 16
#define GRID  444           // 148 SMs x 3 resident CTAs: ONE wave, persistent
#define REM   (BATCH - (BATCH / GRID) * GRID)   // 2048 - 4*444 = 272

__device__ float g_partial[BATCH];
__device__ int   g_count = 0;

// 2 ping-pong buffers x 3 components x 2048 floats = 48 KB
#define SMEM_BYTES (2 * 3 * CH * 4)

extern __shared__ __align__(16) float sstage[];

__device__ __forceinline__ void phaseA(const float* __restrict__ s3,
                                       const float* __restrict__ s2,
                                       const float* __restrict__ df,
                                       int b, int half,
                                       float* __restrict__ bx,
                                       float* __restrict__ by,
                                       float* __restrict__ bz,
                                       int t)
{
    const float* __restrict__ s3b = s3 + (size_t)b * (3 * NPTS);
    const float* __restrict__ s2b = s2 + (size_t)b * (3 * NPTS);
    const float* __restrict__ dfb = df + (size_t)b * (2 * NPTS);
    #pragma unroll
    for (int k = 0; k < LEPT; k++) {
        const int i = t + k * TPB;          // 0..2047, coalesced
        const int g = i + half * CH;
        float vx = 0.f, vy = 0.f, vz = 0.f;
        if (g < NPTS) {                      // only g==4095 (half==1) fails
            float r3  = s3b[g];
            float th3 = s3b[g + NPTS];
            float ph3 = s3b[g + 2 * NPTS];
            float r2  = s2b[g];
            float th2 = s2b[g + NPTS];
            float ph2 = s2b[g + 2 * NPTS];
            float dt  = dfb[g];
            float dp  = dfb[g + NPTS];

            float st, ct, sp, cp;
            __sincosf(th3 + dt, &st, &ct);
            __sincosf(ph3 + dp, &sp, &cp);
            float rst = r3 * st;
            vx = rst * cp; vy = rst * sp; vz = r3 * ct;
            __sincosf(th2, &st, &ct);
            __sincosf(ph2, &sp, &cp);
            rst = r2 * st;
            vx -= rst * cp; vy -= rst * sp; vz -= r2 * ct;
        }
        bx[i] = vx; by[i] = vy; bz[i] = vz;
    }
}

__global__ void __launch_bounds__(TPB, 3)
mpd_fused_kernel(const float* __restrict__ o3,
                 const float* __restrict__ s3,
                 const float* __restrict__ o2,
                 const float* __restrict__ s2,
                 const float* __restrict__ df,
                 float* __restrict__ out)
{
    __shared__ float wt[2][3][NWARP];        // ping-pong warp-total slots
    __shared__ float red[NWARP];
    __shared__ int   is_last;

    const int t = threadIdx.x;
    const unsigned lane = t & 31u;
    const unsigned warp = t >> 5;

    // this CTA's batch count: CTAs [0,REM) get one extra
    const int nb = BATCH / GRID + (blockIdx.x < REM ? 1 : 0);
    const int nq = 2 * nb;                   // quarters (half-batches)

    // prologue: quarter 0 = (batch blockIdx.x, half 0) -> buffer 0
    phaseA(s3, s2, df, blockIdx.x, 0,
           sstage, sstage + CH, sstage + 2 * CH, t);
    __syncthreads();

    const int base = LEPT * t;               // float4 slot, 16B aligned
    float offx = 0.f, offy = 0.f, offz = 0.f;
    float acc = 0.f;

    for (int j = 0; j < nq; j++) {
        const int s = j & 1;                 // current buffer / wt slot
        const int b = blockIdx.x + (j >> 1) * GRID;
        const int half = j & 1;              // quarter parity == buffer parity

        float* cbx = sstage + (s * 3 + 0) * CH;
        float* cby = sstage + (s * 3 + 1) * CH;
        float* cbz = sstage + (s * 3 + 2) * CH;

        // issue next quarter's load burst FIRST (covers this quarter's scan;
        // crosses batch boundaries seamlessly)
        if (j + 1 < nq) {
            const int jn = j + 1;
            const int ns = jn & 1;
            phaseA(s3, s2, df, blockIdx.x + (jn >> 1) * GRID, jn & 1,
                   sstage + (ns * 3 + 0) * CH,
                   sstage + (ns * 3 + 1) * CH,
                   sstage + (ns * 3 + 2) * CH, t);
        }

        // batch start: reset running offset + acc seed
        if (half == 0) {
            offx = o3[b * 3 + 0] - o2[b * 3 + 0];
            offy = o3[b * 3 + 1] - o2[b * 3 + 1];
            offz = o3[b * 3 + 2] - o2[b * 3 + 2];
            acc = (t == 0) ? fabsf(offx) + fabsf(offy) + fabsf(offz) : 0.f;
        }

        // ---- B_a: ONE smem read (kept in regs), totals + warp scan ----
        float4 X = *reinterpret_cast<const float4*>(cbx + base);
        float4 Y = *reinterpret_cast<const float4*>(cby + base);
        float4 Z = *reinterpret_cast<const float4*>(cbz + base);
        const float tx = (X.x + X.y) + (X.z + X.w);
        const float ty = (Y.x + Y.y) + (Y.z + Y.w);
        const float tz = (Z.x + Z.y) + (Z.z + Z.w);

        float ix = tx, iy = ty, iz = tz;
        #pragma unroll
        for (int o = 1; o < 32; o <<= 1) {
            float ax = __shfl_up_sync(0xFFFFFFFFu, ix, o);
            float ay = __shfl_up_sync(0xFFFFFFFFu, iy, o);
            float az = __shfl_up_sync(0xFFFFFFFFu, iz, o);
            if (lane >= (unsigned)o) { ix += ax; iy += ay; iz += az; }
        }
        if (lane == 31) {
            wt[s][0][warp] = ix; wt[s][1][warp] = iy; wt[s][2][warp] = iz;
        }
        __syncthreads();                     // fences wt[s] AND buffer reuse

        // ---- B_b: cross-warp scan + abs sweep from registers ----
        float px = (lane < NWARP) ? wt[s][0][lane] : 0.f;
        float py = (lane < NWARP) ? wt[s][1][lane] : 0.f;
        float pz = (lane < NWARP) ? wt[s][2][lane] : 0.f;
        #pragma unroll
        for (int o = 1; o < NWARP; o <<= 1) {
            float ax = __shfl_up_sync(0xFFFFFFFFu, px, o);
            float ay = __shfl_up_sync(0xFFFFFFFFu, py, o);
            float az = __shfl_up_sync(0xFFFFFFFFu, pz, o);
            if (lane >= (unsigned)o) { px += ax; py += ay; pz += az; }
        }
        const unsigned src = (warp == 0) ? 0u : (warp - 1u);
        float wpx = __shfl_sync(0xFFFFFFFFu, px, src);
        float wpy = __shfl_sync(0xFFFFFFFFu, py, src);
        float wpz = __shfl_sync(0xFFFFFFFFu, pz, src);

        float ox = offx + (ix - tx) + ((warp == 0) ? 0.f : wpx);
        float oy = offy + (iy - ty) + ((warp == 0) ? 0.f : wpy);
        float oz = offz + (iz - tz) + ((warp == 0) ? 0.f : wpz);

        const int gbase = half * CH + base;
        float xs[LEPT] = {X.x, X.y, X.z, X.w};
        float ys[LEPT] = {Y.x, Y.y, Y.z, Y.w};
        float zs[LEPT] = {Z.x, Z.y, Z.z, Z.w};
        #pragma unroll
        for (int k = 0; k < LEPT; k++) {
            ox += xs[k]; oy += ys[k]; oz += zs[k];
            if (gbase + k < NPTS)
                acc += fabsf(ox) + fabsf(oy) + fabsf(oz);
        }

        // advance running offset by this quarter's block total
        offx += __shfl_sync(0xFFFFFFFFu, px, NWARP - 1);
        offy += __shfl_sync(0xFFFFFFFFu, py, NWARP - 1);
        offz += __shfl_sync(0xFFFFFFFFu, pz, NWARP - 1);

        // batch end: block-reduce acc -> g_partial[b]
        if (half == 1) {
            float a = acc;
            #pragma unroll
            for (int o = 16; o > 0; o >>= 1)
                a += __shfl_down_sync(0xFFFFFFFFu, a, o);
            if (lane == 0) red[warp] = a;
            __syncthreads();
            if (warp == 0) {
                float v = (lane < NWARP) ? red[lane] : 0.f;
                #pragma unroll
                for (int o = 16; o > 0; o >>= 1)
                    v += __shfl_down_sync(0xFFFFFFFFu, v, o);
                if (lane == 0) g_partial[b] = v * (1.0f / (NPTS + 1));
            }
        }
    }

    // ---- fused deterministic final reduction in the last CTA ----
    if (t == 0) {
        __threadfence();
        int ticket = atomicAdd(&g_count, 1);
        is_last = (ticket == GRID - 1) ? 1 : 0;
    }
    __syncthreads();
    if (is_last) {
        float a = __ldcg(&g_partial[t])
                + __ldcg(&g_partial[t + TPB])
                + __ldcg(&g_partial[t + 2 * TPB])
                + __ldcg(&g_partial[t + 3 * TPB]);
        #pragma unroll
        for (int o = 16; o > 0; o >>= 1)
            a += __shfl_down_sync(0xFFFFFFFFu, a, o);
        if (lane == 0) red[warp] = a;
        __syncthreads();
        if (warp == 0) {
            float v = (lane < NWARP) ? red[lane] : 0.f;
            #pragma unroll
            for (int o = 16; o > 0; o >>= 1)
                v += __shfl_down_sync(0xFFFFFFFFu, v, o);
            if (lane == 0) {
                out[0] = v;
                atomicExch(&g_count, 0);   // reset for next graph replay
            }
        }
    }
}

extern "C" void kernel_launch(void* const* d_in, const int* in_sizes, int n_in,
                              void* d_out, int out_size)
{
    const float* o3 = (const float*)d_in[0];  // origin_3D        (B,3,1)
    const float* s3 = (const float*)d_in[1];  // spherical_3D     (B,3,N)
    const float* o2 = (const float*)d_in[2];  // origin_2D        (B,3,1)
    const float* s2 = (const float*)d_in[3];  // spherical_2D     (B,3,N)
    const float* df = (const float*)d_in[4];  // deformation_field(B,2,N)
    float* out = (float*)d_out;

    cudaFuncSetAttribute(mpd_fused_kernel,
                         cudaFuncAttributeMaxDynamicSharedMemorySize, SMEM_BYTES);
    mpd_fused_kernel<<<GRID, TPB, SMEM_BYTES>>>(o3, s3, o2, s2, df, out);
}

// round 16
// speedup vs baseline: 1.3345x; 1.0048x over previous
#include <cuda_runtime.h>

#define BATCH 2048
#define NPTS  4095
#define TPB   512
#define HALF  2048
#define LEPT  4
#define NWARP (TPB/32)     // 16

__device__ float g_partial[BATCH];
__device__ int   g_count = 0;

// dynamic smem: two staging buffers of 3*2048 floats = 2 * 24 KB = 48 KB
#define SMEM_BYTES (2 * 3 * HALF * 4)

extern __shared__ __align__(16) float sstage[];

__global__ void __launch_bounds__(TPB, 3)
mpd_fused_kernel(const float* __restrict__ o3,
                 const float* __restrict__ s3,
                 const float* __restrict__ o2,
                 const float* __restrict__ s2,
                 const float* __restrict__ df,
                 float* __restrict__ out)
{
    // ---- convoy-breaking skew: first-wave CTAs only, one-time cost ----
    // co-resident triple on an SM = {b, b+148, b+296} -> classes 0,1,2
    if (blockIdx.x < 3 * 148) {
        const long long k = blockIdx.x / 148;
        if (k != 0 && threadIdx.x == 0) {
            const long long s = clock64();
            const long long d = k * 3000;     // ~1.5us per class @ ~2GHz
            while (clock64() - s < d) { }
        }
        __syncthreads();   // whole CTA waits on the skew
    }

    float* b0x = sstage;
    float* b0y = b0x + HALF;
    float* b0z = b0y + HALF;
    float* b1x = sstage + 3 * HALF;
    float* b1y = b1x + HALF;
    float* b1z = b1y + HALF;
    __shared__ float wt0[3][NWARP], wt1[3][NWARP];
    __shared__ float red[NWARP];
    __shared__ int   is_last;

    const int b = blockIdx.x;
    const int t = threadIdx.x;
    const unsigned lane = t & 31u;
    const unsigned warp = t >> 5;

    const float* __restrict__ s3b = s3 + (size_t)b * (3 * NPTS);
    const float* __restrict__ s2b = s2 + (size_t)b * (3 * NPTS);
    const float* __restrict__ dfb = df + (size_t)b * (2 * NPTS);

    // ================= Phase A0: elements [0,2048) -> buf0 =================
    #pragma unroll
    for (int k = 0; k < LEPT; k++) {
        const int i = t + k * TPB;             // 0..2047, coalesced
        float r3  = s3b[i];
        float th3 = s3b[i + NPTS];
        float ph3 = s3b[i + 2 * NPTS];
        float r2  = s2b[i];
        float th2 = s2b[i + NPTS];
        float ph2 = s2b[i + 2 * NPTS];
        float dt  = dfb[i];
        float dp  = dfb[i + NPTS];

        float st, ct, sp, cp;
        __sincosf(th3 + dt, &st, &ct);
        __sincosf(ph3 + dp, &sp, &cp);
        float rst = r3 * st;
        float vx = rst * cp, vy = rst * sp, vz = r3 * ct;
        __sincosf(th2, &st, &ct);
        __sincosf(ph2, &sp, &cp);
        rst = r2 * st;
        b0x[i] = vx - rst * cp;
        b0y[i] = vy - rst * sp;
        b0z[i] = vz - r2 * ct;
    }
    __syncthreads();                            // bar 1

    // ====== Phase A1: elements [2048,4096) -> buf1 (loads issued BEFORE
    //        any pass-0 scan work, so DRAM stays busy during B0a) ======
    #pragma unroll
    for (int k = 0; k < LEPT; k++) {
        const int i = t + k * TPB;              // 0..2047
        const int g = i + HALF;
        float vx = 0.f, vy = 0.f, vz = 0.f;
        if (g < NPTS) {                          // only g==4095 fails
            float r3  = s3b[g];
            float th3 = s3b[g + NPTS];
            float ph3 = s3b[g + 2 * NPTS];
            float r2  = s2b[g];
            float th2 = s2b[g + NPTS];
            float ph2 = s2b[g + 2 * NPTS];
            float dt  = dfb[g];
            float dp  = dfb[g + NPTS];

            float st, ct, sp, cp;
            __sincosf(th3 + dt, &st, &ct);
            __sincosf(ph3 + dp, &sp, &cp);
            float rst = r3 * st;
            vx = rst * cp; vy = rst * sp; vz = r3 * ct;
            __sincosf(th2, &st, &ct);
            __sincosf(ph2, &sp, &cp);
            rst = r2 * st;
            vx -= rst * cp; vy -= rst * sp; vz -= r2 * ct;
        }
        b1x[i] = vx; b1y[i] = vy; b1z[i] = vz;
    }

    // origin deltas (tiny loads; L2-resident after wave 1)
    const float dx = o3[b * 3 + 0] - o2[b * 3 + 0];
    const float dy = o3[b * 3 + 1] - o2[b * 3 + 1];
    const float dz = o3[b * 3 + 2] - o2[b * 3 + 2];
    float offx = dx, offy = dy, offz = dz;      // running offset (incl. origin)

    float acc = 0.f;
    if (t == 0) acc = fabsf(dx) + fabsf(dy) + fabsf(dz);   // j=0 (origin)

    const int base = LEPT * t;                  // 16B-aligned float4 slot

    // ================= B0a: sum sweep + warp scan (buf0) =================
    float tx0, ty0, tz0;
    {
        float4 X = *reinterpret_cast<const float4*>(b0x + base);
        float4 Y = *reinterpret_cast<const float4*>(b0y + base);
        float4 Z = *reinterpret_cast<const float4*>(b0z + base);
        tx0 = (X.x + X.y) + (X.z + X.w);
        ty0 = (Y.x + Y.y) + (Y.z + Y.w);
        tz0 = (Z.x + Z.y) + (Z.z + Z.w);
    }
    float ix0 = tx0, iy0 = ty0, iz0 = tz0;
    #pragma unroll
    for (int o = 1; o < 32; o <<= 1) {
        float ax = __shfl_up_sync(0xFFFFFFFFu, ix0, o);
        float ay = __shfl_up_sync(0xFFFFFFFFu, iy0, o);
        float az = __shfl_up_sync(0xFFFFFFFFu, iz0, o);
        if (lane >= (unsigned)o) { ix0 += ax; iy0 += ay; iz0 += az; }
    }
    if (lane == 31) { wt0[0][warp] = ix0; wt0[1][warp] = iy0; wt0[2][warp] = iz0; }
    __syncthreads();                            // bar 2 (also fences buf1 stores)

    // ================= B0b: warp-total scan + abs sweep (buf0) ===========
    {
        float px = (lane < NWARP) ? wt0[0][lane] : 0.f;
        float py = (lane < NWARP) ? wt0[1][lane] : 0.f;
        float pz = (lane < NWARP) ? wt0[2][lane] : 0.f;
        #pragma unroll
        for (int o = 1; o < NWARP; o <<= 1) {
            float ax = __shfl_up_sync(0xFFFFFFFFu, px, o);
            float ay = __shfl_up_sync(0xFFFFFFFFu, py, o);
            float az = __shfl_up_sync(0xFFFFFFFFu, pz, o);
            if (lane >= (unsigned)o) { px += ax; py += ay; pz += az; }
        }
        const unsigned src = (warp == 0) ? 0u : (warp - 1u);
        float wpx = __shfl_sync(0xFFFFFFFFu, px, src);
        float wpy = __shfl_sync(0xFFFFFFFFu, py, src);
        float wpz = __shfl_sync(0xFFFFFFFFu, pz, src);
        float ox = offx + (ix0 - tx0) + ((warp == 0) ? 0.f : wpx);
        float oy = offy + (iy0 - ty0) + ((warp == 0) ? 0.f : wpy);
        float oz = offz + (iz0 - tz0) + ((warp == 0) ? 0.f : wpz);

        float4 X = *reinterpret_cast<const float4*>(b0x + base);
        float4 Y = *reinterpret_cast<const float4*>(b0y + base);
        float4 Z = *reinterpret_cast<const float4*>(b0z + base);
        float xs[LEPT] = {X.x, X.y, X.z, X.w};
        float ys[LEPT] = {Y.x, Y.y, Y.z, Y.w};
        float zs[LEPT] = {Z.x, Z.y, Z.z, Z.w};
        #pragma unroll
        for (int k = 0; k < LEPT; k++) {
            ox += xs[k]; oy += ys[k]; oz += zs[k];
            acc += fabsf(ox) + fabsf(oy) + fabsf(oz);   // all pass-0 idx valid
        }

        // advance running offset by pass-0 block total
        offx += __shfl_sync(0xFFFFFFFFu, px, NWARP - 1);
        offy += __shfl_sync(0xFFFFFFFFu, py, NWARP - 1);
        offz += __shfl_sync(0xFFFFFFFFu, pz, NWARP - 1);
    }

    // ================= B1a: sum sweep + warp scan (buf1) =================
    float tx1, ty1, tz1;
    {
        float4 X = *reinterpret_cast<const float4*>(b1x + base);
        float4 Y = *reinterpret_cast<const float4*>(b1y + base);
        float4 Z = *reinterpret_cast<const float4*>(b1z + base);
        tx1 = (X.x + X.y) + (X.z + X.w);
        ty1 = (Y.x + Y.y) + (Y.z + Y.w);
        tz1 = (Z.x + Z.y) + (Z.z + Z.w);
    }
    float ix1 = tx1, iy1 = ty1, iz1 = tz1;
    #pragma unroll
    for (int o = 1; o < 32; o <<= 1) {
        float ax = __shfl_up_sync(0xFFFFFFFFu, ix1, o);
        float ay = __shfl_up_sync(0xFFFFFFFFu, iy1, o);
        float az = __shfl_up_sync(0xFFFFFFFFu, iz1, o);
        if (lane >= (unsigned)o) { ix1 += ax; iy1 += ay; iz1 += az; }
    }
    if (lane == 31) { wt1[0][warp] = ix1; wt1[1][warp] = iy1; wt1[2][warp] = iz1; }
    __syncthreads();                            // bar 3

    // ================= B1b: warp-total scan + abs sweep (buf1) ===========
    {
        float px = (lane < NWARP) ? wt1[0][lane] : 0.f;
        float py = (lane < NWARP) ? wt1[1][lane] : 0.f;
        float pz = (lane < NWARP) ? wt1[2][lane] : 0.f;
        #pragma unroll
        for (int o = 1; o < NWARP; o <<= 1) {
            float ax = __shfl_up_sync(0xFFFFFFFFu, px, o);
            float ay = __shfl_up_sync(0xFFFFFFFFu, py, o);
            float az = __shfl_up_sync(0xFFFFFFFFu, pz, o);
            if (lane >= (unsigned)o) { px += ax; py += ay; pz += az; }
        }
        const unsigned src = (warp == 0) ? 0u : (warp - 1u);
        float wpx = __shfl_sync(0xFFFFFFFFu, px, src);
        float wpy = __shfl_sync(0xFFFFFFFFu, py, src);
        float wpz = __shfl_sync(0xFFFFFFFFu, pz, src);
        float ox = offx + (ix1 - tx1) + ((warp == 0) ? 0.f : wpx);
        float oy = offy + (iy1 - ty1) + ((warp == 0) ? 0.f : wpy);
        float oz = offz + (iz1 - tz1) + ((warp == 0) ? 0.f : wpz);

        float4 X = *reinterpret_cast<const float4*>(b1x + base);
        float4 Y = *reinterpret_cast<const float4*>(b1y + base);
        float4 Z = *reinterpret_cast<const float4*>(b1z + base);
        float xs[LEPT] = {X.x, X.y, X.z, X.w};
        float ys[LEPT] = {Y.x, Y.y, Y.z, Y.w};
        float zs[LEPT] = {Z.x, Z.y, Z.z, Z.w};
        #pragma unroll
        for (int k = 0; k < LEPT; k++) {
            ox += xs[k]; oy += ys[k]; oz += zs[k];
            if (HALF + base + k < NPTS)
                acc += fabsf(ox) + fabsf(oy) + fabsf(oz);
        }
    }

    // ================= block reduce =================
    #pragma unroll
    for (int o = 16; o > 0; o >>= 1)
        acc += __shfl_down_sync(0xFFFFFFFFu, acc, o);
    if (lane == 0) red[warp] = acc;
    __syncthreads();
    if (warp == 0) {
        float a = (lane < NWARP) ? red[lane] : 0.f;
        #pragma unroll
        for (int o = 16; o > 0; o >>= 1)
            a += __shfl_down_sync(0xFFFFFFFFu, a, o);
        if (lane == 0) g_partial[b] = a * (1.0f / (NPTS + 1));
    }

    // ================= fused deterministic final reduction =================
    if (t == 0) {
        __threadfence();
        int ticket = atomicAdd(&g_count, 1);
        is_last = (ticket == (int)gridDim.x - 1) ? 1 : 0;
    }
    __syncthreads();
    if (is_last) {
        float a = __ldcg(&g_partial[t])
                + __ldcg(&g_partial[t + TPB])
                + __ldcg(&g_partial[t + 2 * TPB])
                + __ldcg(&g_partial[t + 3 * TPB]);
        #pragma unroll
        for (int o = 16; o > 0; o >>= 1)
            a += __shfl_down_sync(0xFFFFFFFFu, a, o);
        if (lane == 0) red[warp] = a;
        __syncthreads();
        if (warp == 0) {
            float v = (lane < NWARP) ? red[lane] : 0.f;
            #pragma unroll
            for (int o = 16; o > 0; o >>= 1)
                v += __shfl_down_sync(0xFFFFFFFFu, v, o);
            if (lane == 0) {
                out[0] = v;
                atomicExch(&g_count, 0);   // reset for next graph replay
            }
        }
    }
}

extern "C" void kernel_launch(void* const* d_in, const int* in_sizes, int n_in,
                              void* d_out, int out_size)
{
    const float* o3 = (const float*)d_in[0];  // origin_3D        (B,3,1)
    const float* s3 = (const float*)d_in[1];  // spherical_3D     (B,3,N)
    const float* o2 = (const float*)d_in[2];  // origin_2D        (B,3,1)
    const float* s2 = (const float*)d_in[3];  // spherical_2D     (B,3,N)
    const float* df = (const float*)d_in[4];  // deformation_field(B,2,N)
    float* out = (float*)d_out;

    cudaFuncSetAttribute(mpd_fused_kernel,
                         cudaFuncAttributeMaxDynamicSharedMemorySize, SMEM_BYTES);
    mpd_fused_kernel<<<BATCH, TPB, SMEM_BYTES>>>(o3, s3, o2, s2, df, out);
}

// round 17
// speedup vs baseline: 1.3465x; 1.0090x over previous
#include <cuda_runtime.h>

#define BATCH 2048
#define NPTS  4095
#define TPB   512
#define HALF  2048
#define LEPT  4
#define NWARP (TPB/32)      // 16
#define GRID  444           // 148 SMs x 3 resident CTAs, persistent
#define NBMIN (BATCH / GRID)            // 4
#define REM   (BATCH - NBMIN * GRID)    // 272

__device__ float g_cta[GRID];
__device__ int   g_count = 0;

// two staging buffers of 3*2048 floats = 48 KB
#define SMEM_BYTES (2 * 3 * HALF * 4)
extern __shared__ __align__(16) float sstage[];

__device__ __forceinline__ void phaseA(const float* __restrict__ s3p,
                                       const float* __restrict__ s2p,
                                       const float* __restrict__ dfp,
                                       int half,
                                       float* __restrict__ bx,
                                       float* __restrict__ by,
                                       float* __restrict__ bz,
                                       int t)
{
    #pragma unroll
    for (int k = 0; k < LEPT; k++) {
        const int i = t + k * TPB;          // 0..2047, coalesced
        const int g = i + half * HALF;
        float vx = 0.f, vy = 0.f, vz = 0.f;
        if (g < NPTS) {                      // only g==4095 (half==1) fails
            float r3  = s3p[g];
            float th3 = s3p[g + NPTS];
            float ph3 = s3p[g + 2 * NPTS];
            float r2  = s2p[g];
            float th2 = s2p[g + NPTS];
            float ph2 = s2p[g + 2 * NPTS];
            float dt  = dfp[g];
            float dp  = dfp[g + NPTS];

            float st, ct, sp, cp;
            __sincosf(th3 + dt, &st, &ct);
            __sincosf(ph3 + dp, &sp, &cp);
            float rst = r3 * st;
            vx = rst * cp; vy = rst * sp; vz = r3 * ct;
            __sincosf(th2, &st, &ct);
            __sincosf(ph2, &sp, &cp);
            rst = r2 * st;
            vx -= rst * cp; vy -= rst * sp; vz -= r2 * ct;
        }
        bx[i] = vx; by[i] = vy; bz[i] = vz;
    }
}

// One quarter's scan+abs. Reads staged float4s ONCE (register-carried).
// wt: [3][NWARP] slot for this quarter parity. Contains ONE __syncthreads().
__device__ __forceinline__ void processB(const float* __restrict__ bx,
                                         const float* __restrict__ by,
                                         const float* __restrict__ bz,
                                         float wt[3][NWARP],
                                         int base, unsigned lane, unsigned warp,
                                         bool tail,
                                         float& offx, float& offy, float& offz,
                                         float& acc)
{
    float4 X = *reinterpret_cast<const float4*>(bx + base);
    float4 Y = *reinterpret_cast<const float4*>(by + base);
    float4 Z = *reinterpret_cast<const float4*>(bz + base);
    const float tx = (X.x + X.y) + (X.z + X.w);
    const float ty = (Y.x + Y.y) + (Y.z + Y.w);
    const float tz = (Z.x + Z.y) + (Z.z + Z.w);

    float ix = tx, iy = ty, iz = tz;
    #pragma unroll
    for (int o = 1; o < 32; o <<= 1) {
        float ax = __shfl_up_sync(0xFFFFFFFFu, ix, o);
        float ay = __shfl_up_sync(0xFFFFFFFFu, iy, o);
        float az = __shfl_up_sync(0xFFFFFFFFu, iz, o);
        if (lane >= (unsigned)o) { ix += ax; iy += ay; iz += az; }
    }
    if (lane == 31) { wt[0][warp] = ix; wt[1][warp] = iy; wt[2][warp] = iz; }
    __syncthreads();

    float px = (lane < NWARP) ? wt[0][lane] : 0.f;
    float py = (lane < NWARP) ? wt[1][lane] : 0.f;
    float pz = (lane < NWARP) ? wt[2][lane] : 0.f;
    #pragma unroll
    for (int o = 1; o < NWARP; o <<= 1) {
        float ax = __shfl_up_sync(0xFFFFFFFFu, px, o);
        float ay = __shfl_up_sync(0xFFFFFFFFu, py, o);
        float az = __shfl_up_sync(0xFFFFFFFFu, pz, o);
        if (lane >= (unsigned)o) { px += ax; py += ay; pz += az; }
    }
    const unsigned src = (warp == 0) ? 0u : (warp - 1u);
    float wpx = __shfl_sync(0xFFFFFFFFu, px, src);
    float wpy = __shfl_sync(0xFFFFFFFFu, py, src);
    float wpz = __shfl_sync(0xFFFFFFFFu, pz, src);

    float ox = offx + (ix - tx) + ((warp == 0) ? 0.f : wpx);
    float oy = offy + (iy - ty) + ((warp == 0) ? 0.f : wpy);
    float oz = offz + (iz - tz) + ((warp == 0) ? 0.f : wpz);

    float xs[LEPT] = {X.x, X.y, X.z, X.w};
    float ys[LEPT] = {Y.x, Y.y, Y.z, Y.w};
    float zs[LEPT] = {Z.x, Z.y, Z.z, Z.w};
    #pragma unroll
    for (int k = 0; k < LEPT; k++) {
        ox += xs[k]; oy += ys[k]; oz += zs[k];
        if (!tail || (base + k) < (NPTS - HALF))   // tail: only idx 2047 of half-1 invalid
            acc += fabsf(ox) + fabsf(oy) + fabsf(oz);
    }

    offx += __shfl_sync(0xFFFFFFFFu, px, NWARP - 1);
    offy += __shfl_sync(0xFFFFFFFFu, py, NWARP - 1);
    offz += __shfl_sync(0xFFFFFFFFu, pz, NWARP - 1);
}

__global__ void __launch_bounds__(TPB, 3)
mpd_fused_kernel(const float* __restrict__ o3,
                 const float* __restrict__ s3,
                 const float* __restrict__ o2,
                 const float* __restrict__ s2,
                 const float* __restrict__ df,
                 float* __restrict__ out)
{
    float* b0x = sstage;
    float* b0y = b0x + HALF;
    float* b0z = b0y + HALF;
    float* b1x = sstage + 3 * HALF;
    float* b1y = b1x + HALF;
    float* b1z = b1y + HALF;
    __shared__ float wt0[3][NWARP], wt1[3][NWARP];
    __shared__ float red[NWARP];
    __shared__ int   is_last;

    const int t = threadIdx.x;
    const unsigned lane = t & 31u;
    const unsigned warp = t >> 5;

    const int nb = NBMIN + (blockIdx.x < REM ? 1 : 0);

    // incremental batch pointers (constant stride per batch step)
    const float* s3p = s3 + (size_t)blockIdx.x * (3 * NPTS);
    const float* s2p = s2 + (size_t)blockIdx.x * (3 * NPTS);
    const float* dfp = df + (size_t)blockIdx.x * (2 * NPTS);
    const size_t DS  = (size_t)GRID * (3 * NPTS);
    const size_t DDF = (size_t)GRID * (2 * NPTS);
    int b = blockIdx.x;

    // prologue: (batch0, half0) -> buf0
    phaseA(s3p, s2p, dfp, 0, b0x, b0y, b0z, t);
    __syncthreads();

    float acc = 0.f;
    float offx, offy, offz;

    for (int w = 0; w < nb; w++) {
        const bool last_batch = (w == nb - 1);
        const int base = LEPT * t;

        // -------- quarter h=0 --------
        // prefetch this batch's half-1 into buf1 (covers h0 scan)
        phaseA(s3p, s2p, dfp, 1, b1x, b1y, b1z, t);

        // batch init: origin delta + j=0 term
        offx = o3[b * 3 + 0] - o2[b * 3 + 0];
        offy = o3[b * 3 + 1] - o2[b * 3 + 1];
        offz = o3[b * 3 + 2] - o2[b * 3 + 2];
        if (t == 0) acc += fabsf(offx) + fabsf(offy) + fabsf(offz);

        processB(b0x, b0y, b0z, wt0, base, lane, warp, false,
                 offx, offy, offz, acc);

        // -------- quarter h=1 --------
        // prefetch NEXT batch's half-0 into buf0 (covers h1 scan)
        if (!last_batch)
            phaseA(s3p + DS, s2p + DS, dfp + DDF, 0, b0x, b0y, b0z, t);

        processB(b1x, b1y, b1z, wt1, base, lane, warp, true,
                 offx, offy, offz, acc);

        s3p += DS; s2p += DS; dfp += DDF; b += GRID;
    }

    // ---- ONE block reduce per CTA (acc summed across all its batches) ----
    acc *= (1.0f / (NPTS + 1));
    #pragma unroll
    for (int o = 16; o > 0; o >>= 1)
        acc += __shfl_down_sync(0xFFFFFFFFu, acc, o);
    if (lane == 0) red[warp] = acc;
    __syncthreads();
    if (warp == 0) {
        float a = (lane < NWARP) ? red[lane] : 0.f;
        #pragma unroll
        for (int o = 16; o > 0; o >>= 1)
            a += __shfl_down_sync(0xFFFFFFFFu, a, o);
        if (lane == 0) g_cta[blockIdx.x] = a;
    }

    // ---- fused deterministic final reduction in the last CTA ----
    if (t == 0) {
        __threadfence();
        int ticket = atomicAdd(&g_count, 1);
        is_last = (ticket == GRID - 1) ? 1 : 0;
    }
    __syncthreads();
    if (is_last) {
        float a = (t < GRID) ? __ldcg(&g_cta[t]) : 0.f;
        #pragma unroll
        for (int o = 16; o > 0; o >>= 1)
            a += __shfl_down_sync(0xFFFFFFFFu, a, o);
        if (lane == 0) red[warp] = a;
        __syncthreads();
        if (warp == 0) {
            float v = (lane < NWARP) ? red[lane] : 0.f;
            #pragma unroll
            for (int o = 16; o > 0; o >>= 1)
                v += __shfl_down_sync(0xFFFFFFFFu, v, o);
            if (lane == 0) {
                out[0] = v;
                atomicExch(&g_count, 0);   // reset for next graph replay
            }
        }
    }
}

extern "C" void kernel_launch(void* const* d_in, const int* in_sizes, int n_in,
                              void* d_out, int out_size)
{
    const float* o3 = (const float*)d_in[0];  // origin_3D        (B,3,1)
    const float* s3 = (const float*)d_in[1];  // spherical_3D     (B,3,N)
    const float* o2 = (const float*)d_in[2];  // origin_2D        (B,3,1)
    const float* s2 = (const float*)d_in[3];  // spherical_2D     (B,3,N)
    const float* df = (const float*)d_in[4];  // deformation_field(B,2,N)
    float* out = (float*)d_out;

    cudaFuncSetAttribute(mpd_fused_kernel,
                         cudaFuncAttributeMaxDynamicSharedMemorySize, SMEM_BYTES);
    mpd_fused_kernel<<<GRID, TPB, SMEM_BYTES>>>(o3, s3, o2, s2, df, out);
}